// round 2
// baseline (speedup 1.0000x reference)
#include <cuda_runtime.h>
#include <math.h>

#define N_NODES 50000
#define F_IN    512
#define H1      8
#define C1      16
#define F1      128   // H1*C1
#define C2      40
#define E_IN    800000
#define E_TOT   850000   // + self loops
#define NEG_SLOPE 0.2f

// ---------------- scratch (device globals; no allocation allowed) ----------
__device__ int   g_is64;
__device__ int   g_src[E_TOT];
__device__ int   g_dst[E_TOT];
__device__ float g_h1[N_NODES * F1];          // layer-1 features  [N,128]
__device__ float g_asrc1[N_NODES * H1];
__device__ float g_adst1[N_NODES * H1];
__device__ float g_m1[N_NODES * H1];
__device__ float g_d1[N_NODES * H1];
__device__ float g_e1[(size_t)E_TOT * H1];    // per-edge e / ex   [E,8]
__device__ float g_out1[N_NODES * F1];        // layer-1 aggregated (then elu)
__device__ float g_h2[N_NODES * C2];
__device__ float g_asrc2[N_NODES];
__device__ float g_adst2[N_NODES];
__device__ float g_m2[N_NODES];
__device__ float g_d2[N_NODES];
__device__ float g_e2[E_TOT];
__device__ float g_out2[N_NODES * C2];

// ---------------- helpers ---------------------------------------------------
__device__ __forceinline__ void atomicMaxFloat(float* addr, float val) {
    if (val >= 0.0f) atomicMax((int*)addr, __float_as_int(val));
    else             atomicMin((unsigned int*)addr, __float_as_uint(val));
}

// ---------------- dtype probe + edge decode ---------------------------------
// If edge_index is int64, every odd 32-bit word in the first row is the high
// half of a value in [0, 50000) => zero. If int32, odd words are random node
// ids. OR-reduce the first 8192 words' odd positions.
__global__ void probe_kernel(const int* __restrict__ ei_w) {
    __shared__ int red[256];
    int t = threadIdx.x;
    int acc = 0;
    for (int i = t; i < 4096; i += 256) acc |= ei_w[2 * i + 1];
    red[t] = acc;
    __syncthreads();
    for (int s = 128; s > 0; s >>= 1) {
        if (t < s) red[t] |= red[t + s];
        __syncthreads();
    }
    if (t == 0) g_is64 = (red[0] == 0) ? 1 : 0;
}

__global__ void convert_kernel(const void* __restrict__ ei_raw) {
    int e = blockIdx.x * blockDim.x + threadIdx.x;
    if (e >= E_TOT) return;
    int src, dst;
    if (e < E_IN) {
        if (g_is64) {
            const long long* ei = (const long long*)ei_raw;
            src = (int)ei[e];
            dst = (int)ei[E_IN + e];
        } else {
            const int* ei = (const int*)ei_raw;
            src = ei[e];
            dst = ei[E_IN + e];
        }
    } else {
        src = dst = e - E_IN;   // self loop
    }
    g_src[e] = src;
    g_dst[e] = dst;
}

// ---------------- init: zero accumulators, -inf maxima ----------------------
__global__ void init_kernel() {
    int i = blockIdx.x * blockDim.x + threadIdx.x;
    if (i < N_NODES * F1) g_out1[i] = 0.0f;
    if (i < N_NODES * C2) g_out2[i] = 0.0f;
    if (i < N_NODES * H1) { g_d1[i] = 0.0f; g_m1[i] = -INFINITY; }
    if (i < N_NODES)      { g_d2[i] = 0.0f; g_m2[i] = -INFINITY; }
}

// ---------------- GEMM1: h1 = X[N,512] @ W1[512,128] ------------------------
__global__ __launch_bounds__(256)
void gemm1_kernel(const float* __restrict__ X, const float* __restrict__ W) {
    __shared__ float As[8][128];   // As[k][m]
    __shared__ float Bs[8][128];   // Bs[k][n]
    const int block_row = blockIdx.x * 128;
    const int tid = threadIdx.x;               // 256 threads
    const int tr = tid / 16, tc = tid % 16;    // 16x16 threads, 8x8 microtile

    float acc[8][8];
#pragma unroll
    for (int i = 0; i < 8; i++)
#pragma unroll
        for (int j = 0; j < 8; j++) acc[i][j] = 0.0f;

    const int a_m  = tid / 2;            // 0..127
    const int a_kb = (tid % 2) * 4;      // 0 or 4
    const int gm   = block_row + a_m;
    const int b_k  = tid / 32;           // 0..7
    const int b_n  = (tid % 32) * 4;     // 0..124

    for (int k0 = 0; k0 < F_IN; k0 += 8) {
        float4 av = make_float4(0.f, 0.f, 0.f, 0.f);
        if (gm < N_NODES)
            av = *reinterpret_cast<const float4*>(X + (size_t)gm * F_IN + k0 + a_kb);
        As[a_kb + 0][a_m] = av.x;
        As[a_kb + 1][a_m] = av.y;
        As[a_kb + 2][a_m] = av.z;
        As[a_kb + 3][a_m] = av.w;

        float4 bv = *reinterpret_cast<const float4*>(W + (size_t)(k0 + b_k) * F1 + b_n);
        *reinterpret_cast<float4*>(&Bs[b_k][b_n]) = bv;
        __syncthreads();

#pragma unroll
        for (int k = 0; k < 8; k++) {
            float a[8], b[8];
            *reinterpret_cast<float4*>(&a[0]) = *reinterpret_cast<float4*>(&As[k][tr * 8]);
            *reinterpret_cast<float4*>(&a[4]) = *reinterpret_cast<float4*>(&As[k][tr * 8 + 4]);
            *reinterpret_cast<float4*>(&b[0]) = *reinterpret_cast<float4*>(&Bs[k][tc * 8]);
            *reinterpret_cast<float4*>(&b[4]) = *reinterpret_cast<float4*>(&Bs[k][tc * 8 + 4]);
#pragma unroll
            for (int i = 0; i < 8; i++)
#pragma unroll
                for (int j = 0; j < 8; j++) acc[i][j] += a[i] * b[j];
        }
        __syncthreads();
    }

#pragma unroll
    for (int i = 0; i < 8; i++) {
        int m = block_row + tr * 8 + i;
        if (m < N_NODES) {
            float* dst = g_h1 + (size_t)m * F1 + tc * 8;
            *reinterpret_cast<float4*>(dst)     = make_float4(acc[i][0], acc[i][1], acc[i][2], acc[i][3]);
            *reinterpret_cast<float4*>(dst + 4) = make_float4(acc[i][4], acc[i][5], acc[i][6], acc[i][7]);
        }
    }
}

// ---------------- attention dots, layer 1 -----------------------------------
__global__ void attn1_kernel(const float* __restrict__ att_src,
                             const float* __restrict__ att_dst) {
    int id = blockIdx.x * blockDim.x + threadIdx.x;   // n*8 + h
    if (id >= N_NODES * H1) return;
    int n = id >> 3, h = id & 7;
    const float* row = g_h1 + (size_t)n * F1 + h * C1;
    float s = 0.f, d = 0.f;
#pragma unroll
    for (int c = 0; c < C1; c++) {
        float v = row[c];
        s += v * att_src[h * C1 + c];
        d += v * att_dst[h * C1 + c];
    }
    g_asrc1[id] = s;
    g_adst1[id] = d;
}

// ---------------- edge passes, layer 1 --------------------------------------
__global__ void edgeA1_kernel() {
    int id = blockIdx.x * blockDim.x + threadIdx.x;   // e*8 + h
    if (id >= E_TOT * H1) return;
    int e = id >> 3, h = id & 7;
    int src = g_src[e], dst = g_dst[e];
    float v = g_asrc1[src * H1 + h] + g_adst1[dst * H1 + h];
    v = (v > 0.f) ? v : NEG_SLOPE * v;                // leaky relu
    g_e1[id] = v;
    atomicMaxFloat(&g_m1[dst * H1 + h], v);
}

__global__ void edgeB1_kernel() {
    int id = blockIdx.x * blockDim.x + threadIdx.x;
    if (id >= E_TOT * H1) return;
    int e = id >> 3, h = id & 7;
    int dst = g_dst[e];
    float ex = __expf(g_e1[id] - g_m1[dst * H1 + h]);
    g_e1[id] = ex;
    atomicAdd(&g_d1[dst * H1 + h], ex);
}

__global__ void edgeC1_kernel() {
    int gid  = blockIdx.x * blockDim.x + threadIdx.x;
    int e    = gid >> 5;
    int lane = gid & 31;
    if (e >= E_TOT) return;
    int src = g_src[e], dst = g_dst[e];
    const float* hrow = g_h1 + (size_t)src * F1;
    float* orow = g_out1 + (size_t)dst * F1;
#pragma unroll
    for (int i = 0; i < 4; i++) {
        int c = lane + i * 32;
        int h = c >> 4;
        float alpha = g_e1[(size_t)e * H1 + h] / (g_d1[dst * H1 + h] + 1e-16f);
        atomicAdd(orow + c, hrow[c] * alpha);
    }
}

// ---------------- bias + ELU -------------------------------------------------
__global__ void elu_kernel(const float* __restrict__ b1) {
    int i = blockIdx.x * blockDim.x + threadIdx.x;
    if (i >= N_NODES * F1) return;
    float v = g_out1[i] + b1[i & (F1 - 1)];
    g_out1[i] = (v > 0.f) ? v : (__expf(v) - 1.0f);
}

// ---------------- GEMM2: h2 = elu_out[N,128] @ W2[128,40] -------------------
__global__ __launch_bounds__(256)
void gemm2_kernel(const float* __restrict__ W2) {
    __shared__ float Ws[F1 * C2];     // 128*40 = 5120 floats
    __shared__ float Hs[32][F1];      // 32 nodes
    const int t  = threadIdx.x;
    const int nb = blockIdx.x * 32;
    for (int i = t; i < F1 * C2; i += 256) Ws[i] = W2[i];
    for (int i = t; i < 32 * F1; i += 256) {
        int r = i >> 7, c = i & 127;
        int n = nb + r;
        Hs[r][c] = (n < N_NODES) ? g_out1[(size_t)n * F1 + c] : 0.f;
    }
    __syncthreads();
    const int ln = t >> 3;            // local node 0..31
    const int c0 = (t & 7) * 5;       // 5 cols each
    float acc[5] = {0.f, 0.f, 0.f, 0.f, 0.f};
    for (int k = 0; k < F1; k++) {
        float hv = Hs[ln][k];
#pragma unroll
        for (int j = 0; j < 5; j++) acc[j] += hv * Ws[k * C2 + c0 + j];
    }
    int n = nb + ln;
    if (n < N_NODES) {
#pragma unroll
        for (int j = 0; j < 5; j++) g_h2[(size_t)n * C2 + c0 + j] = acc[j];
    }
}

// ---------------- attention dots, layer 2 (warp per node) -------------------
__global__ void attn2_kernel(const float* __restrict__ att_src,
                             const float* __restrict__ att_dst) {
    int gid  = blockIdx.x * blockDim.x + threadIdx.x;
    int n    = gid >> 5;
    int lane = gid & 31;
    if (n >= N_NODES) return;
    float s = 0.f, d = 0.f;
    for (int c = lane; c < C2; c += 32) {
        float v = g_h2[(size_t)n * C2 + c];
        s += v * att_src[c];
        d += v * att_dst[c];
    }
#pragma unroll
    for (int o = 16; o > 0; o >>= 1) {
        s += __shfl_xor_sync(0xFFFFFFFF, s, o);
        d += __shfl_xor_sync(0xFFFFFFFF, d, o);
    }
    if (lane == 0) { g_asrc2[n] = s; g_adst2[n] = d; }
}

// ---------------- edge passes, layer 2 --------------------------------------
__global__ void edgeA2_kernel() {
    int e = blockIdx.x * blockDim.x + threadIdx.x;
    if (e >= E_TOT) return;
    int src = g_src[e], dst = g_dst[e];
    float v = g_asrc2[src] + g_adst2[dst];
    v = (v > 0.f) ? v : NEG_SLOPE * v;
    g_e2[e] = v;
    atomicMaxFloat(&g_m2[dst], v);
}

__global__ void edgeB2_kernel() {
    int e = blockIdx.x * blockDim.x + threadIdx.x;
    if (e >= E_TOT) return;
    int dst = g_dst[e];
    float ex = __expf(g_e2[e] - g_m2[dst]);
    g_e2[e] = ex;
    atomicAdd(&g_d2[dst], ex);
}

__global__ void edgeC2_kernel() {
    int gid  = blockIdx.x * blockDim.x + threadIdx.x;
    int e    = gid >> 5;
    int lane = gid & 31;
    if (e >= E_TOT) return;
    int src = g_src[e], dst = g_dst[e];
    float alpha = g_e2[e] / (g_d2[dst] + 1e-16f);
    const float* hrow = g_h2 + (size_t)src * C2;
    float* orow = g_out2 + (size_t)dst * C2;
    {
        int c = lane;
        if (c < C2) atomicAdd(orow + c, hrow[c] * alpha);
    }
    {
        int c = lane + 32;
        if (c < C2) atomicAdd(orow + c, hrow[c] * alpha);
    }
}

// ---------------- final: +b2 and log_softmax over 40 classes ----------------
__global__ void final_kernel(const float* __restrict__ b2, float* __restrict__ out) {
    int gid  = blockIdx.x * blockDim.x + threadIdx.x;
    int n    = gid >> 5;
    int lane = gid & 31;
    if (n >= N_NODES) return;
    float v1 = g_out2[(size_t)n * C2 + lane] + b2[lane];                 // lane < 32 < 40
    float v2 = (lane < C2 - 32) ? g_out2[(size_t)n * C2 + lane + 32] + b2[lane + 32]
                                : -INFINITY;
    float m = fmaxf(v1, v2);
#pragma unroll
    for (int o = 16; o > 0; o >>= 1) m = fmaxf(m, __shfl_xor_sync(0xFFFFFFFF, m, o));
    float s = __expf(v1 - m) + ((lane < C2 - 32) ? __expf(v2 - m) : 0.f);
#pragma unroll
    for (int o = 16; o > 0; o >>= 1) s += __shfl_xor_sync(0xFFFFFFFF, s, o);
    float lse = m + logf(s);
    out[(size_t)n * C2 + lane] = v1 - lse;
    if (lane < C2 - 32) out[(size_t)n * C2 + lane + 32] = v2 - lse;
}

// ---------------- launcher ---------------------------------------------------
extern "C" void kernel_launch(void* const* d_in, const int* in_sizes, int n_in,
                              void* d_out, int out_size) {
    const float* x        = (const float*)d_in[0];
    const void*  ei       = d_in[1];
    const float* W1       = (const float*)d_in[2];
    const float* att_src1 = (const float*)d_in[3];
    const float* att_dst1 = (const float*)d_in[4];
    const float* b1       = (const float*)d_in[5];
    const float* W2       = (const float*)d_in[6];
    const float* att_src2 = (const float*)d_in[7];
    const float* att_dst2 = (const float*)d_in[8];
    const float* b2       = (const float*)d_in[9];
    float*       out      = (float*)d_out;

    const int T = 256;

    probe_kernel<<<1, 256>>>((const int*)ei);
    convert_kernel<<<(E_TOT + T - 1) / T, T>>>(ei);

    init_kernel<<<(N_NODES * F1 + T - 1) / T, T>>>();

    gemm1_kernel<<<(N_NODES + 127) / 128, 256>>>(x, W1);
    attn1_kernel<<<(N_NODES * H1 + T - 1) / T, T>>>(att_src1, att_dst1);

    edgeA1_kernel<<<(E_TOT * H1 + T - 1) / T, T>>>();
    edgeB1_kernel<<<(E_TOT * H1 + T - 1) / T, T>>>();
    edgeC1_kernel<<<((size_t)E_TOT * 32 + T - 1) / T, T>>>();

    elu_kernel<<<(N_NODES * F1 + T - 1) / T, T>>>(b1);

    gemm2_kernel<<<(N_NODES + 31) / 32, 256>>>(W2);
    attn2_kernel<<<((size_t)N_NODES * 32 + T - 1) / T, T>>>(att_src2, att_dst2);

    edgeA2_kernel<<<(E_TOT + T - 1) / T, T>>>();
    edgeB2_kernel<<<(E_TOT + T - 1) / T, T>>>();
    edgeC2_kernel<<<((size_t)E_TOT * 32 + T - 1) / T, T>>>();

    final_kernel<<<((size_t)N_NODES * 32 + T - 1) / T, T>>>(b2, out);
}

// round 3
// speedup vs baseline: 1.6249x; 1.6249x over previous
#include <cuda_runtime.h>
#include <math.h>

#define N_NODES 50000
#define F_IN    512
#define H1      8
#define C1      16
#define F1      128   // H1*C1
#define C2      40
#define E_IN    800000
#define E_TOT   850000   // + self loops
#define NEG_SLOPE 0.2f
#define NB_TILES 98      // ceil(N_NODES/512)

// ---------------- scratch (device globals; no allocation allowed) ----------
__device__ int   g_is64;
__device__ int   g_src[E_TOT];
__device__ int   g_dst[E_TOT];
__device__ int   g_deg[N_NODES];
__device__ int   g_cur[N_NODES];
__device__ int   g_rowptr[N_NODES + 1];
__device__ int   g_bsum[NB_TILES];
__device__ int   g_bscan[NB_TILES];
__device__ int   g_esrc[E_TOT];               // CSR-by-dst src list
__device__ float g_h1[N_NODES * F1];          // layer-1 features  [N,128]
__device__ float g_asrc1[N_NODES * H1];
__device__ float g_adst1[N_NODES * H1];
__device__ float g_out1[N_NODES * F1];        // layer-1 out (bias+elu fused)
__device__ float g_h2[N_NODES * C2];
__device__ float g_asrc2[N_NODES];
__device__ float g_adst2[N_NODES];

// ---------------- dtype probe + edge decode ---------------------------------
__global__ void probe_kernel(const int* __restrict__ ei_w) {
    __shared__ int red[256];
    int t = threadIdx.x;
    int acc = 0;
    for (int i = t; i < 4096; i += 256) acc |= ei_w[2 * i + 1];
    red[t] = acc;
    __syncthreads();
    for (int s = 128; s > 0; s >>= 1) {
        if (t < s) red[t] |= red[t + s];
        __syncthreads();
    }
    if (t == 0) g_is64 = (red[0] == 0) ? 1 : 0;
}

__global__ void convert_kernel(const void* __restrict__ ei_raw) {
    int e = blockIdx.x * blockDim.x + threadIdx.x;
    if (e >= E_TOT) return;
    int src, dst;
    if (e < E_IN) {
        if (g_is64) {
            const long long* ei = (const long long*)ei_raw;
            src = (int)ei[e];
            dst = (int)ei[E_IN + e];
        } else {
            const int* ei = (const int*)ei_raw;
            src = ei[e];
            dst = ei[E_IN + e];
        }
    } else {
        src = dst = e - E_IN;   // self loop
    }
    g_src[e] = src;
    g_dst[e] = dst;
}

// ---------------- init + CSR build ------------------------------------------
__global__ void init_kernel() {
    int i = blockIdx.x * blockDim.x + threadIdx.x;
    if (i < N_NODES) { g_deg[i] = 0; g_cur[i] = 0; }
}

__global__ void hist_kernel() {
    int e = blockIdx.x * blockDim.x + threadIdx.x;
    if (e >= E_TOT) return;
    atomicAdd(&g_deg[g_dst[e]], 1);
}

// tile-wise exclusive scan: 512 elems per block
__global__ __launch_bounds__(512)
void scan1_kernel() {
    int t = threadIdx.x;
    int lane = t & 31, wid = t >> 5;
    int gid = blockIdx.x * 512 + t;
    int v = (gid < N_NODES) ? g_deg[gid] : 0;
    int x = v;
#pragma unroll
    for (int o = 1; o < 32; o <<= 1) {
        int y = __shfl_up_sync(0xFFFFFFFF, x, o);
        if (lane >= o) x += y;
    }
    __shared__ int wsum[16];
    if (lane == 31) wsum[wid] = x;
    __syncthreads();
    if (t < 16) {
        int s = wsum[t];
#pragma unroll
        for (int o = 1; o < 16; o <<= 1) {
            int y = __shfl_up_sync(0xFFFF, s, o);
            if (t >= o) s += y;
        }
        wsum[t] = s;
    }
    __syncthreads();
    int base = (wid > 0) ? wsum[wid - 1] : 0;
    if (gid < N_NODES) g_rowptr[gid] = base + x - v;     // exclusive within tile
    if (t == 511) g_bsum[blockIdx.x] = base + x;         // tile total
}

// scan of the 98 tile totals (1 warp)
__global__ void scan2_kernel() {
    int t = threadIdx.x;   // 32 threads
    int v[4]; int tot = 0;
#pragma unroll
    for (int j = 0; j < 4; j++) {
        int idx = t * 4 + j;
        v[j] = (idx < NB_TILES) ? g_bsum[idx] : 0;
        tot += v[j];
    }
    int x = tot;
#pragma unroll
    for (int o = 1; o < 32; o <<= 1) {
        int y = __shfl_up_sync(0xFFFFFFFF, x, o);
        if (t >= o) x += y;
    }
    int run = x - tot;   // exclusive
#pragma unroll
    for (int j = 0; j < 4; j++) {
        int idx = t * 4 + j;
        if (idx < NB_TILES) g_bscan[idx] = run;
        run += v[j];
    }
}

__global__ void scan3_kernel() {
    int i = blockIdx.x * blockDim.x + threadIdx.x;
    if (i < N_NODES) g_rowptr[i] += g_bscan[i >> 9];
    if (i == 0) g_rowptr[N_NODES] = E_TOT;
}

__global__ void scatter_kernel() {
    int e = blockIdx.x * blockDim.x + threadIdx.x;
    if (e >= E_TOT) return;
    int dst = g_dst[e];
    int pos = g_rowptr[dst] + atomicAdd(&g_cur[dst], 1);
    g_esrc[pos] = g_src[e];
}

// ---------------- GEMM1: h1 = X[N,512] @ W1[512,128] ------------------------
__global__ __launch_bounds__(256)
void gemm1_kernel(const float* __restrict__ X, const float* __restrict__ W) {
    __shared__ float As[8][128];
    __shared__ float Bs[8][128];
    const int block_row = blockIdx.x * 128;
    const int tid = threadIdx.x;
    const int tr = tid / 16, tc = tid % 16;

    float acc[8][8];
#pragma unroll
    for (int i = 0; i < 8; i++)
#pragma unroll
        for (int j = 0; j < 8; j++) acc[i][j] = 0.0f;

    const int a_m  = tid / 2;
    const int a_kb = (tid % 2) * 4;
    const int gm   = block_row + a_m;
    const int b_k  = tid / 32;
    const int b_n  = (tid % 32) * 4;

    for (int k0 = 0; k0 < F_IN; k0 += 8) {
        float4 av = make_float4(0.f, 0.f, 0.f, 0.f);
        if (gm < N_NODES)
            av = *reinterpret_cast<const float4*>(X + (size_t)gm * F_IN + k0 + a_kb);
        As[a_kb + 0][a_m] = av.x;
        As[a_kb + 1][a_m] = av.y;
        As[a_kb + 2][a_m] = av.z;
        As[a_kb + 3][a_m] = av.w;

        float4 bv = *reinterpret_cast<const float4*>(W + (size_t)(k0 + b_k) * F1 + b_n);
        *reinterpret_cast<float4*>(&Bs[b_k][b_n]) = bv;
        __syncthreads();

#pragma unroll
        for (int k = 0; k < 8; k++) {
            float a[8], b[8];
            *reinterpret_cast<float4*>(&a[0]) = *reinterpret_cast<float4*>(&As[k][tr * 8]);
            *reinterpret_cast<float4*>(&a[4]) = *reinterpret_cast<float4*>(&As[k][tr * 8 + 4]);
            *reinterpret_cast<float4*>(&b[0]) = *reinterpret_cast<float4*>(&Bs[k][tc * 8]);
            *reinterpret_cast<float4*>(&b[4]) = *reinterpret_cast<float4*>(&Bs[k][tc * 8 + 4]);
#pragma unroll
            for (int i = 0; i < 8; i++)
#pragma unroll
                for (int j = 0; j < 8; j++) acc[i][j] += a[i] * b[j];
        }
        __syncthreads();
    }

#pragma unroll
    for (int i = 0; i < 8; i++) {
        int m = block_row + tr * 8 + i;
        if (m < N_NODES) {
            float* dst = g_h1 + (size_t)m * F1 + tc * 8;
            *reinterpret_cast<float4*>(dst)     = make_float4(acc[i][0], acc[i][1], acc[i][2], acc[i][3]);
            *reinterpret_cast<float4*>(dst + 4) = make_float4(acc[i][4], acc[i][5], acc[i][6], acc[i][7]);
        }
    }
}

// ---------------- attention dots, layer 1 -----------------------------------
__global__ void attn1_kernel(const float* __restrict__ att_src,
                             const float* __restrict__ att_dst) {
    int id = blockIdx.x * blockDim.x + threadIdx.x;   // n*8 + h
    if (id >= N_NODES * H1) return;
    int n = id >> 3, h = id & 7;
    const float* row = g_h1 + (size_t)n * F1 + h * C1;
    float s = 0.f, d = 0.f;
#pragma unroll
    for (int c = 0; c < C1; c++) {
        float v = row[c];
        s += v * att_src[h * C1 + c];
        d += v * att_dst[h * C1 + c];
    }
    g_asrc1[id] = s;
    g_adst1[id] = d;
}

// ---------------- layer-1 aggregation: warp per dst node, online softmax ----
__global__ __launch_bounds__(256)
void agg1_kernel(const float* __restrict__ b1) {
    int gid  = blockIdx.x * blockDim.x + threadIdx.x;
    int n    = gid >> 5;
    int lane = gid & 31;
    if (n >= N_NODES) return;
    int h = lane >> 2;                 // 4 consecutive channels per lane, one head
    float adst = g_adst1[n * H1 + h];
    int beg = g_rowptr[n], end = g_rowptr[n + 1];

    float m = -INFINITY, d = 0.f;
    float ax = 0.f, ay = 0.f, az = 0.f, aw = 0.f;
    for (int i = beg; i < end; i++) {
        int src = __ldg(&g_esrc[i]);
        float v = g_asrc1[src * H1 + h] + adst;
        v = (v > 0.f) ? v : NEG_SLOPE * v;            // leaky relu
        float mn = fmaxf(m, v);
        float s  = __expf(m - mn);
        float w  = __expf(v - mn);
        const float4 hv = *reinterpret_cast<const float4*>(g_h1 + (size_t)src * F1 + lane * 4);
        d  = d  * s + w;
        ax = ax * s + w * hv.x;
        ay = ay * s + w * hv.y;
        az = az * s + w * hv.z;
        aw = aw * s + w * hv.w;
        m = mn;
    }
    float inv = 1.f / (d + 1e-16f);
    const float4 bv = *reinterpret_cast<const float4*>(b1 + lane * 4);
    float o0 = ax * inv + bv.x;
    float o1 = ay * inv + bv.y;
    float o2 = az * inv + bv.z;
    float o3 = aw * inv + bv.w;
    o0 = (o0 > 0.f) ? o0 : (__expf(o0) - 1.f);        // elu
    o1 = (o1 > 0.f) ? o1 : (__expf(o1) - 1.f);
    o2 = (o2 > 0.f) ? o2 : (__expf(o2) - 1.f);
    o3 = (o3 > 0.f) ? o3 : (__expf(o3) - 1.f);
    *reinterpret_cast<float4*>(g_out1 + (size_t)n * F1 + lane * 4) =
        make_float4(o0, o1, o2, o3);
}

// ---------------- GEMM2: h2 = out1[N,128] @ W2[128,40] ----------------------
__global__ __launch_bounds__(256)
void gemm2_kernel(const float* __restrict__ W2) {
    __shared__ float Ws[F1 * C2];
    __shared__ float Hs[32][F1];
    const int t  = threadIdx.x;
    const int nb = blockIdx.x * 32;
    for (int i = t; i < F1 * C2; i += 256) Ws[i] = W2[i];
    for (int i = t; i < 32 * F1; i += 256) {
        int r = i >> 7, c = i & 127;
        int n = nb + r;
        Hs[r][c] = (n < N_NODES) ? g_out1[(size_t)n * F1 + c] : 0.f;
    }
    __syncthreads();
    const int ln = t >> 3;
    const int c0 = (t & 7) * 5;
    float acc[5] = {0.f, 0.f, 0.f, 0.f, 0.f};
    for (int k = 0; k < F1; k++) {
        float hv = Hs[ln][k];
#pragma unroll
        for (int j = 0; j < 5; j++) acc[j] += hv * Ws[k * C2 + c0 + j];
    }
    int n = nb + ln;
    if (n < N_NODES) {
#pragma unroll
        for (int j = 0; j < 5; j++) g_h2[(size_t)n * C2 + c0 + j] = acc[j];
    }
}

// ---------------- attention dots, layer 2 (warp per node) -------------------
__global__ void attn2_kernel(const float* __restrict__ att_src,
                             const float* __restrict__ att_dst) {
    int gid  = blockIdx.x * blockDim.x + threadIdx.x;
    int n    = gid >> 5;
    int lane = gid & 31;
    if (n >= N_NODES) return;
    float s = 0.f, d = 0.f;
    for (int c = lane; c < C2; c += 32) {
        float v = g_h2[(size_t)n * C2 + c];
        s += v * att_src[c];
        d += v * att_dst[c];
    }
#pragma unroll
    for (int o = 16; o > 0; o >>= 1) {
        s += __shfl_xor_sync(0xFFFFFFFF, s, o);
        d += __shfl_xor_sync(0xFFFFFFFF, d, o);
    }
    if (lane == 0) { g_asrc2[n] = s; g_adst2[n] = d; }
}

// -------- layer-2 aggregation + bias + log_softmax (warp per dst node) ------
__global__ __launch_bounds__(256)
void agg2_kernel(const float* __restrict__ b2, float* __restrict__ out) {
    int gid  = blockIdx.x * blockDim.x + threadIdx.x;
    int n    = gid >> 5;
    int lane = gid & 31;
    if (n >= N_NODES) return;
    float adst = g_adst2[n];
    int beg = g_rowptr[n], end = g_rowptr[n + 1];

    float m = -INFINITY, d = 0.f;
    float a1 = 0.f, a2 = 0.f;
    for (int i = beg; i < end; i++) {
        int src = __ldg(&g_esrc[i]);
        float v = g_asrc2[src] + adst;
        v = (v > 0.f) ? v : NEG_SLOPE * v;
        float mn = fmaxf(m, v);
        float s  = __expf(m - mn);
        float w  = __expf(v - mn);
        const float* hrow = g_h2 + (size_t)src * C2;
        float h1v = hrow[lane];
        float h2v = (lane < C2 - 32) ? hrow[lane + 32] : 0.f;
        d  = d  * s + w;
        a1 = a1 * s + w * h1v;
        a2 = a2 * s + w * h2v;
        m = mn;
    }
    float inv = 1.f / (d + 1e-16f);
    float v1 = a1 * inv + b2[lane];
    float v2 = (lane < C2 - 32) ? (a2 * inv + b2[lane + 32]) : -INFINITY;

    float mm = fmaxf(v1, v2);
#pragma unroll
    for (int o = 16; o > 0; o >>= 1) mm = fmaxf(mm, __shfl_xor_sync(0xFFFFFFFF, mm, o));
    float ss = __expf(v1 - mm) + ((lane < C2 - 32) ? __expf(v2 - mm) : 0.f);
#pragma unroll
    for (int o = 16; o > 0; o >>= 1) ss += __shfl_xor_sync(0xFFFFFFFF, ss, o);
    float lse = mm + logf(ss);
    out[(size_t)n * C2 + lane] = v1 - lse;
    if (lane < C2 - 32) out[(size_t)n * C2 + lane + 32] = v2 - lse;
}

// ---------------- launcher ---------------------------------------------------
extern "C" void kernel_launch(void* const* d_in, const int* in_sizes, int n_in,
                              void* d_out, int out_size) {
    const float* x        = (const float*)d_in[0];
    const void*  ei       = d_in[1];
    const float* W1       = (const float*)d_in[2];
    const float* att_src1 = (const float*)d_in[3];
    const float* att_dst1 = (const float*)d_in[4];
    const float* b1       = (const float*)d_in[5];
    const float* W2       = (const float*)d_in[6];
    const float* att_src2 = (const float*)d_in[7];
    const float* att_dst2 = (const float*)d_in[8];
    const float* b2       = (const float*)d_in[9];
    float*       out      = (float*)d_out;

    const int T = 256;

    probe_kernel<<<1, 256>>>((const int*)ei);
    convert_kernel<<<(E_TOT + T - 1) / T, T>>>(ei);
    init_kernel<<<(N_NODES + T - 1) / T, T>>>();
    hist_kernel<<<(E_TOT + T - 1) / T, T>>>();
    scan1_kernel<<<NB_TILES, 512>>>();
    scan2_kernel<<<1, 32>>>();
    scan3_kernel<<<(N_NODES + T - 1) / T, T>>>();
    scatter_kernel<<<(E_TOT + T - 1) / T, T>>>();

    gemm1_kernel<<<(N_NODES + 127) / 128, 256>>>(x, W1);
    attn1_kernel<<<(N_NODES * H1 + T - 1) / T, T>>>(att_src1, att_dst1);
    agg1_kernel<<<((size_t)N_NODES * 32 + T - 1) / T, T>>>(b1);

    gemm2_kernel<<<(N_NODES + 31) / 32, 256>>>(W2);
    attn2_kernel<<<((size_t)N_NODES * 32 + T - 1) / T, T>>>(att_src2, att_dst2);
    agg2_kernel<<<((size_t)N_NODES * 32 + T - 1) / T, T>>>(b2, out);
}

// round 6
// speedup vs baseline: 2.2178x; 1.3648x over previous
#include <cuda_runtime.h>
#include <cuda_bf16.h>
#include <math.h>
#include <stdint.h>

#define N_NODES 50000
#define F_IN    512
#define H1      8
#define C1      16
#define F1      128   // H1*C1
#define C2      40
#define E_IN    800000
#define E_TOT   850000   // + self loops
#define NEG_SLOPE 0.2f
#define NB_TILES 98      // ceil(N_NODES/512)

// ---------------- scratch (device globals; no allocation allowed) ----------
__device__ int   g_is64;
__device__ int   g_src[E_TOT];
__device__ int   g_dst[E_TOT];
__device__ int   g_deg[N_NODES];
__device__ int   g_cur[N_NODES];
__device__ int   g_rowptr[N_NODES + 1];
__device__ int   g_bsum[NB_TILES];
__device__ int   g_bscan[NB_TILES];
__device__ int   g_esrc[E_TOT];               // CSR-by-dst src list
__device__ float g_h1[N_NODES * F1];          // layer-1 features  [N,128]
__device__ float g_asrc1[N_NODES * H1];
__device__ float g_adst1[N_NODES * H1];
__device__ float g_out1[N_NODES * F1];        // layer-1 out (bias+elu fused)
__device__ float g_h2[N_NODES * C2];
__device__ float g_asrc2[N_NODES];
__device__ float g_adst2[N_NODES];
__device__ __nv_bfloat16 g_whi[F1 * F_IN];    // W1^T split-hi  [n=128][k=512]
__device__ __nv_bfloat16 g_wlo[F1 * F_IN];    // W1^T split-lo

// ---------------- MMA helpers ------------------------------------------------
__device__ __forceinline__ uint32_t smem_to_u32(const void* p) {
    uint32_t a;
    asm("{ .reg .u64 t; cvta.to.shared.u64 t, %1; cvt.u32.u64 %0, t; }"
        : "=r"(a) : "l"(p));
    return a;
}
__device__ __forceinline__ void ldsm_x4(uint32_t* r, uint32_t addr) {
    asm volatile("ldmatrix.sync.aligned.m8n8.x4.shared.b16 {%0,%1,%2,%3}, [%4];"
        : "=r"(r[0]), "=r"(r[1]), "=r"(r[2]), "=r"(r[3]) : "r"(addr));
}
__device__ __forceinline__ void ldsm_x2(uint32_t* r, uint32_t addr) {
    asm volatile("ldmatrix.sync.aligned.m8n8.x2.shared.b16 {%0,%1}, [%2];"
        : "=r"(r[0]), "=r"(r[1]) : "r"(addr));
}
__device__ __forceinline__ void mma16816(float* d, const uint32_t* a,
                                         const uint32_t* b) {
    asm volatile("mma.sync.aligned.m16n8k16.row.col.f32.bf16.bf16.f32 "
        "{%0,%1,%2,%3}, {%4,%5,%6,%7}, {%8,%9}, {%0,%1,%2,%3};"
        : "+f"(d[0]), "+f"(d[1]), "+f"(d[2]), "+f"(d[3])
        : "r"(a[0]), "r"(a[1]), "r"(a[2]), "r"(a[3]), "r"(b[0]), "r"(b[1]));
}
__device__ __forceinline__ uint32_t pack_bf2(float a, float b) {
    __nv_bfloat162 p = __floats2bfloat162_rn(a, b);
    return *reinterpret_cast<uint32_t*>(&p);
}

// ---------------- dtype probe + edge decode ---------------------------------
__global__ void probe_kernel(const int* __restrict__ ei_w) {
    __shared__ int red[256];
    int t = threadIdx.x;
    int acc = 0;
    for (int i = t; i < 4096; i += 256) acc |= ei_w[2 * i + 1];
    red[t] = acc;
    __syncthreads();
    for (int s = 128; s > 0; s >>= 1) {
        if (t < s) red[t] |= red[t + s];
        __syncthreads();
    }
    if (t == 0) g_is64 = (red[0] == 0) ? 1 : 0;
}

__global__ void convert_kernel(const void* __restrict__ ei_raw) {
    int e = blockIdx.x * blockDim.x + threadIdx.x;
    if (e >= E_TOT) return;
    int src, dst;
    if (e < E_IN) {
        if (g_is64) {
            const long long* ei = (const long long*)ei_raw;
            src = (int)ei[e];
            dst = (int)ei[E_IN + e];
        } else {
            const int* ei = (const int*)ei_raw;
            src = ei[e];
            dst = ei[E_IN + e];
        }
    } else {
        src = dst = e - E_IN;
    }
    g_src[e] = src;
    g_dst[e] = dst;
}

// ---------------- init + CSR build ------------------------------------------
__global__ void init_kernel() {
    int i = blockIdx.x * blockDim.x + threadIdx.x;
    if (i < N_NODES) { g_deg[i] = 0; g_cur[i] = 0; }
}

__global__ void hist_kernel() {
    int e = blockIdx.x * blockDim.x + threadIdx.x;
    if (e >= E_TOT) return;
    atomicAdd(&g_deg[g_dst[e]], 1);
}

__global__ __launch_bounds__(512)
void scan1_kernel() {
    int t = threadIdx.x;
    int lane = t & 31, wid = t >> 5;
    int gid = blockIdx.x * 512 + t;
    int v = (gid < N_NODES) ? g_deg[gid] : 0;
    int x = v;
#pragma unroll
    for (int o = 1; o < 32; o <<= 1) {
        int y = __shfl_up_sync(0xFFFFFFFF, x, o);
        if (lane >= o) x += y;
    }
    __shared__ int wsum[16];
    if (lane == 31) wsum[wid] = x;
    __syncthreads();
    if (t < 16) {
        int s = wsum[t];
#pragma unroll
        for (int o = 1; o < 16; o <<= 1) {
            int y = __shfl_up_sync(0xFFFF, s, o);
            if (t >= o) s += y;
        }
        wsum[t] = s;
    }
    __syncthreads();
    int base = (wid > 0) ? wsum[wid - 1] : 0;
    if (gid < N_NODES) g_rowptr[gid] = base + x - v;
    if (t == 511) g_bsum[blockIdx.x] = base + x;
}

__global__ void scan2_kernel() {
    int t = threadIdx.x;
    int v[4]; int tot = 0;
#pragma unroll
    for (int j = 0; j < 4; j++) {
        int idx = t * 4 + j;
        v[j] = (idx < NB_TILES) ? g_bsum[idx] : 0;
        tot += v[j];
    }
    int x = tot;
#pragma unroll
    for (int o = 1; o < 32; o <<= 1) {
        int y = __shfl_up_sync(0xFFFFFFFF, x, o);
        if (t >= o) x += y;
    }
    int run = x - tot;
#pragma unroll
    for (int j = 0; j < 4; j++) {
        int idx = t * 4 + j;
        if (idx < NB_TILES) g_bscan[idx] = run;
        run += v[j];
    }
}

__global__ void scan3_kernel() {
    int i = blockIdx.x * blockDim.x + threadIdx.x;
    if (i < N_NODES) g_rowptr[i] += g_bscan[i >> 9];
    if (i == 0) g_rowptr[N_NODES] = E_TOT;
}

__global__ void scatter_kernel() {
    int e = blockIdx.x * blockDim.x + threadIdx.x;
    if (e >= E_TOT) return;
    int dst = g_dst[e];
    int pos = g_rowptr[dst] + atomicAdd(&g_cur[dst], 1);
    g_esrc[pos] = g_src[e];
}

// ---------------- W1 transpose + split --------------------------------------
__global__ void wsplit_kernel(const float* __restrict__ W1) {
    int id = blockIdx.x * blockDim.x + threadIdx.x;  // 128*512
    if (id >= F1 * F_IN) return;
    int n = id & (F1 - 1);
    int k = id >> 7;
    float v = W1[(size_t)k * F1 + n];
    __nv_bfloat16 hi = __float2bfloat16_rn(v);
    float r = v - __bfloat162float(hi);
    g_whi[n * F_IN + k] = hi;
    g_wlo[n * F_IN + k] = __float2bfloat16_rn(r);
}

// ---------------- GEMM1 via mma.sync bf16 split: h1 = X @ W1 ----------------
// CTA: 128x128, K chunks of 64. 8 warps as 4(m) x 2(n); warp tile 32x64.
// smem tiles padded to stride 72 bf16 (144B) => conflict-free ldmatrix.
#define LDT 72
#define TILE_B (128 * LDT * 2)     // 18432 bytes per buffer
#define OFF_A_HI 0
#define OFF_A_LO (TILE_B)
#define OFF_B_HI (2 * TILE_B)
#define OFF_B_LO (3 * TILE_B)
#define SMEM_TOT (4 * TILE_B)

__global__ __launch_bounds__(256)
void gemm1_mma_kernel(const float* __restrict__ X) {
    extern __shared__ char smem[];
    const int t = threadIdx.x;
    const int lane = t & 31, wid = t >> 5;
    const int warp_m = wid & 3, warp_n = wid >> 2;
    const int block_row = blockIdx.x * 128;
    const uint32_t sb = smem_to_u32(smem);

    float acc[2][8][4];
#pragma unroll
    for (int i = 0; i < 2; i++)
#pragma unroll
        for (int j = 0; j < 8; j++)
#pragma unroll
            for (int q = 0; q < 4; q++) acc[i][j][q] = 0.f;

    for (int kt = 0; kt < 8; kt++) {
        const int k0g = kt * 64;
        // ---- A: 128 rows x 64 fp32 -> split hi/lo bf16 ----
#pragma unroll
        for (int i = 0; i < 8; i++) {
            int c = i * 256 + t;          // 0..2047 float4 chunks
            int row = c >> 4;
            int kq = c & 15;
            int grow = block_row + row;
            float4 v = make_float4(0.f, 0.f, 0.f, 0.f);
            if (grow < N_NODES)
                v = *reinterpret_cast<const float4*>(X + (size_t)grow * F_IN + k0g + kq * 4);
            uint2 hi, lo;
            hi.x = pack_bf2(v.x, v.y);
            hi.y = pack_bf2(v.z, v.w);
            __nv_bfloat16 hx = __float2bfloat16_rn(v.x);
            __nv_bfloat16 hy = __float2bfloat16_rn(v.y);
            __nv_bfloat16 hz = __float2bfloat16_rn(v.z);
            __nv_bfloat16 hw = __float2bfloat16_rn(v.w);
            lo.x = pack_bf2(v.x - __bfloat162float(hx), v.y - __bfloat162float(hy));
            lo.y = pack_bf2(v.z - __bfloat162float(hz), v.w - __bfloat162float(hw));
            int off = row * 144 + kq * 8;
            *reinterpret_cast<uint2*>(smem + OFF_A_HI + off) = hi;
            *reinterpret_cast<uint2*>(smem + OFF_A_LO + off) = lo;
        }
        // ---- B: 128 n-rows x 64 bf16 (pre-split) ----
#pragma unroll
        for (int i = 0; i < 4; i++) {
            int c = i * 256 + t;          // 0..1023 16B chunks
            int n = c >> 3;
            int kq = c & 7;
            uint4 vh = *reinterpret_cast<const uint4*>(g_whi + (size_t)n * F_IN + k0g + kq * 8);
            uint4 vl = *reinterpret_cast<const uint4*>(g_wlo + (size_t)n * F_IN + k0g + kq * 8);
            int off = n * 144 + kq * 16;
            *reinterpret_cast<uint4*>(smem + OFF_B_HI + off) = vh;
            *reinterpret_cast<uint4*>(smem + OFF_B_LO + off) = vl;
        }
        __syncthreads();

#pragma unroll
        for (int ks = 0; ks < 4; ks++) {
            const int k0 = ks * 16;
            uint32_t ah[2][4], al[2][4], bh[8][2], bl[8][2];
#pragma unroll
            for (int mf = 0; mf < 2; mf++) {
                int m0 = warp_m * 32 + mf * 16;
                uint32_t addr = (uint32_t)((m0 + (lane & 15)) * 144 +
                                           (k0 + (lane >> 4) * 8) * 2);
                ldsm_x4(ah[mf], sb + OFF_A_HI + addr);
                ldsm_x4(al[mf], sb + OFF_A_LO + addr);
            }
#pragma unroll
            for (int nf = 0; nf < 8; nf++) {
                int n0 = warp_n * 64 + nf * 8;
                uint32_t addr = (uint32_t)((n0 + (lane & 7)) * 144 +
                                           (k0 + ((lane >> 3) & 1) * 8) * 2);
                ldsm_x2(bh[nf], sb + OFF_B_HI + addr);
                ldsm_x2(bl[nf], sb + OFF_B_LO + addr);
            }
#pragma unroll
            for (int mf = 0; mf < 2; mf++)
#pragma unroll
                for (int nf = 0; nf < 8; nf++) {
                    mma16816(acc[mf][nf], ah[mf], bh[nf]);
                    mma16816(acc[mf][nf], ah[mf], bl[nf]);
                    mma16816(acc[mf][nf], al[mf], bh[nf]);
                }
        }
        __syncthreads();
    }

    // ---- epilogue: write fp32 accumulators to g_h1 ----
#pragma unroll
    for (int mf = 0; mf < 2; mf++) {
        int r0 = block_row + warp_m * 32 + mf * 16 + (lane >> 2);
#pragma unroll
        for (int nf = 0; nf < 8; nf++) {
            int col = warp_n * 64 + nf * 8 + (lane & 3) * 2;
            if (r0 < N_NODES)
                *reinterpret_cast<float2*>(g_h1 + (size_t)r0 * F1 + col) =
                    make_float2(acc[mf][nf][0], acc[mf][nf][1]);
            if (r0 + 8 < N_NODES)
                *reinterpret_cast<float2*>(g_h1 + (size_t)(r0 + 8) * F1 + col) =
                    make_float2(acc[mf][nf][2], acc[mf][nf][3]);
        }
    }
}

// ---------------- attention dots, layer 1 -----------------------------------
__global__ void attn1_kernel(const float* __restrict__ att_src,
                             const float* __restrict__ att_dst) {
    int id = blockIdx.x * blockDim.x + threadIdx.x;   // n*8 + h
    if (id >= N_NODES * H1) return;
    int n = id >> 3, h = id & 7;
    const float* row = g_h1 + (size_t)n * F1 + h * C1;
    float s = 0.f, d = 0.f;
#pragma unroll
    for (int c = 0; c < C1; c++) {
        float v = row[c];
        s += v * att_src[h * C1 + c];
        d += v * att_dst[h * C1 + c];
    }
    g_asrc1[id] = s;
    g_adst1[id] = d;
}

// ---------------- layer-1 aggregation: warp per dst node, online softmax ----
__global__ __launch_bounds__(256)
void agg1_kernel(const float* __restrict__ b1) {
    int gid  = blockIdx.x * blockDim.x + threadIdx.x;
    int n    = gid >> 5;
    int lane = gid & 31;
    if (n >= N_NODES) return;
    int h = lane >> 2;
    float adst = g_adst1[n * H1 + h];
    int beg = g_rowptr[n], end = g_rowptr[n + 1];

    float m = -INFINITY, d = 0.f;
    float ax = 0.f, ay = 0.f, az = 0.f, aw = 0.f;
    for (int i = beg; i < end; i++) {
        int src = __ldg(&g_esrc[i]);
        float v = g_asrc1[src * H1 + h] + adst;
        v = (v > 0.f) ? v : NEG_SLOPE * v;
        float mn = fmaxf(m, v);
        float s  = __expf(m - mn);
        float w  = __expf(v - mn);
        const float4 hv = *reinterpret_cast<const float4*>(g_h1 + (size_t)src * F1 + lane * 4);
        d  = d  * s + w;
        ax = ax * s + w * hv.x;
        ay = ay * s + w * hv.y;
        az = az * s + w * hv.z;
        aw = aw * s + w * hv.w;
        m = mn;
    }
    float inv = 1.f / (d + 1e-16f);
    const float4 bv = *reinterpret_cast<const float4*>(b1 + lane * 4);
    float o0 = ax * inv + bv.x;
    float o1 = ay * inv + bv.y;
    float o2 = az * inv + bv.z;
    float o3 = aw * inv + bv.w;
    o0 = (o0 > 0.f) ? o0 : (__expf(o0) - 1.f);
    o1 = (o1 > 0.f) ? o1 : (__expf(o1) - 1.f);
    o2 = (o2 > 0.f) ? o2 : (__expf(o2) - 1.f);
    o3 = (o3 > 0.f) ? o3 : (__expf(o3) - 1.f);
    *reinterpret_cast<float4*>(g_out1 + (size_t)n * F1 + lane * 4) =
        make_float4(o0, o1, o2, o3);
}

// ---------------- GEMM2: h2 = out1[N,128] @ W2[128,40] ----------------------
__global__ __launch_bounds__(256)
void gemm2_kernel(const float* __restrict__ W2) {
    __shared__ float Ws[F1 * C2];
    __shared__ float Hs[32][F1];
    const int t  = threadIdx.x;
    const int nb = blockIdx.x * 32;
    for (int i = t; i < F1 * C2; i += 256) Ws[i] = W2[i];
    for (int i = t; i < 32 * F1; i += 256) {
        int r = i >> 7, c = i & 127;
        int n = nb + r;
        Hs[r][c] = (n < N_NODES) ? g_out1[(size_t)n * F1 + c] : 0.f;
    }
    __syncthreads();
    const int ln = t >> 3;
    const int c0 = (t & 7) * 5;
    float acc[5] = {0.f, 0.f, 0.f, 0.f, 0.f};
    for (int k = 0; k < F1; k++) {
        float hv = Hs[ln][k];
#pragma unroll
        for (int j = 0; j < 5; j++) acc[j] += hv * Ws[k * C2 + c0 + j];
    }
    int n = nb + ln;
    if (n < N_NODES) {
#pragma unroll
        for (int j = 0; j < 5; j++) g_h2[(size_t)n * C2 + c0 + j] = acc[j];
    }
}

// ---------------- attention dots, layer 2 (warp per node) -------------------
__global__ void attn2_kernel(const float* __restrict__ att_src,
                             const float* __restrict__ att_dst) {
    int gid  = blockIdx.x * blockDim.x + threadIdx.x;
    int n    = gid >> 5;
    int lane = gid & 31;
    if (n >= N_NODES) return;
    float s = 0.f, d = 0.f;
    for (int c = lane; c < C2; c += 32) {
        float v = g_h2[(size_t)n * C2 + c];
        s += v * att_src[c];
        d += v * att_dst[c];
    }
#pragma unroll
    for (int o = 16; o > 0; o >>= 1) {
        s += __shfl_xor_sync(0xFFFFFFFF, s, o);
        d += __shfl_xor_sync(0xFFFFFFFF, d, o);
    }
    if (lane == 0) { g_asrc2[n] = s; g_adst2[n] = d; }
}

// -------- layer-2 aggregation + bias + log_softmax (warp per dst node) ------
__global__ __launch_bounds__(256)
void agg2_kernel(const float* __restrict__ b2, float* __restrict__ out) {
    int gid  = blockIdx.x * blockDim.x + threadIdx.x;
    int n    = gid >> 5;
    int lane = gid & 31;
    if (n >= N_NODES) return;
    float adst = g_adst2[n];
    int beg = g_rowptr[n], end = g_rowptr[n + 1];

    float m = -INFINITY, d = 0.f;
    float a1 = 0.f, a2 = 0.f;
    for (int i = beg; i < end; i++) {
        int src = __ldg(&g_esrc[i]);
        float v = g_asrc2[src] + adst;
        v = (v > 0.f) ? v : NEG_SLOPE * v;
        float mn = fmaxf(m, v);
        float s  = __expf(m - mn);
        float w  = __expf(v - mn);
        const float* hrow = g_h2 + (size_t)src * C2;
        float h1v = hrow[lane];
        float h2v = (lane < C2 - 32) ? hrow[lane + 32] : 0.f;
        d  = d  * s + w;
        a1 = a1 * s + w * h1v;
        a2 = a2 * s + w * h2v;
        m = mn;
    }
    float inv = 1.f / (d + 1e-16f);
    float v1 = a1 * inv + b2[lane];
    float v2 = (lane < C2 - 32) ? (a2 * inv + b2[lane + 32]) : -INFINITY;

    float mm = fmaxf(v1, v2);
#pragma unroll
    for (int o = 16; o > 0; o >>= 1) mm = fmaxf(mm, __shfl_xor_sync(0xFFFFFFFF, mm, o));
    float ss = __expf(v1 - mm) + ((lane < C2 - 32) ? __expf(v2 - mm) : 0.f);
#pragma unroll
    for (int o = 16; o > 0; o >>= 1) ss += __shfl_xor_sync(0xFFFFFFFF, ss, o);
    float lse = mm + logf(ss);
    out[(size_t)n * C2 + lane] = v1 - lse;
    if (lane < C2 - 32) out[(size_t)n * C2 + lane + 32] = v2 - lse;
}

// ---------------- launcher ---------------------------------------------------
extern "C" void kernel_launch(void* const* d_in, const int* in_sizes, int n_in,
                              void* d_out, int out_size) {
    const float* x        = (const float*)d_in[0];
    const void*  ei       = d_in[1];
    const float* W1       = (const float*)d_in[2];
    const float* att_src1 = (const float*)d_in[3];
    const float* att_dst1 = (const float*)d_in[4];
    const float* b1       = (const float*)d_in[5];
    const float* W2       = (const float*)d_in[6];
    const float* att_src2 = (const float*)d_in[7];
    const float* att_dst2 = (const float*)d_in[8];
    const float* b2       = (const float*)d_in[9];
    float*       out      = (float*)d_out;

    const int T = 256;

    static int smem_set = 0;
    if (!smem_set) {
        cudaFuncSetAttribute(gemm1_mma_kernel,
                             cudaFuncAttributeMaxDynamicSharedMemorySize, SMEM_TOT);
        smem_set = 1;
    }

    probe_kernel<<<1, 256>>>((const int*)ei);
    convert_kernel<<<(E_TOT + T - 1) / T, T>>>(ei);
    init_kernel<<<(N_NODES + T - 1) / T, T>>>();
    hist_kernel<<<(E_TOT + T - 1) / T, T>>>();
    scan1_kernel<<<NB_TILES, 512>>>();
    scan2_kernel<<<1, 32>>>();
    scan3_kernel<<<(N_NODES + T - 1) / T, T>>>();
    scatter_kernel<<<(E_TOT + T - 1) / T, T>>>();

    wsplit_kernel<<<(F1 * F_IN + T - 1) / T, T>>>(W1);
    gemm1_mma_kernel<<<(N_NODES + 127) / 128, 256, SMEM_TOT>>>(x);
    attn1_kernel<<<(N_NODES * H1 + T - 1) / T, T>>>(att_src1, att_dst1);
    agg1_kernel<<<((size_t)N_NODES * 32 + T - 1) / T, T>>>(b1);

    gemm2_kernel<<<(N_NODES + 31) / 32, 256>>>(W2);
    attn2_kernel<<<((size_t)N_NODES * 32 + T - 1) / T, T>>>(att_src2, att_dst2);
    agg2_kernel<<<((size_t)N_NODES * 32 + T - 1) / T, T>>>(b2, out);
}

// round 7
// speedup vs baseline: 2.4037x; 1.0838x over previous
#include <cuda_runtime.h>
#include <cuda_bf16.h>
#include <math.h>
#include <stdint.h>

#define N_NODES 50000
#define F_IN    512
#define H1      8
#define C1      16
#define F1      128   // H1*C1
#define C2      40
#define E_IN    800000
#define E_TOT   850000   // + self loops
#define NEG_SLOPE 0.2f
#define NB_TILES 98      // ceil(N_NODES/512)

// ---------------- scratch (device globals; no allocation allowed) ----------
__device__ int   g_is64;
__device__ int   g_src[E_TOT];
__device__ int   g_dst[E_TOT];
__device__ int   g_deg[N_NODES];
__device__ int   g_cur[N_NODES];
__device__ int   g_rowptr[N_NODES + 1];
__device__ int   g_bsum[NB_TILES];
__device__ int   g_bscan[NB_TILES];
__device__ int   g_esrc[E_TOT];               // CSR-by-dst src list
__device__ float g_h1[N_NODES * F1];          // layer-1 features  [N,128]
__device__ float g_asrc1[N_NODES * H1];
__device__ float g_adst1[N_NODES * H1];
__device__ float g_out1[N_NODES * F1];        // layer-1 out (bias+elu fused)
__device__ float g_h2[N_NODES * C2];
__device__ float g_asrc2[N_NODES];
__device__ float g_adst2[N_NODES];
__device__ __nv_bfloat16 g_whi[F1 * F_IN];    // W1^T split-hi  [n=128][k=512]
__device__ __nv_bfloat16 g_wlo[F1 * F_IN];    // W1^T split-lo

// ---------------- MMA helpers ------------------------------------------------
__device__ __forceinline__ uint32_t smem_to_u32(const void* p) {
    uint32_t a;
    asm("{ .reg .u64 t; cvta.to.shared.u64 t, %1; cvt.u32.u64 %0, t; }"
        : "=r"(a) : "l"(p));
    return a;
}
__device__ __forceinline__ void ldsm_x4(uint32_t* r, uint32_t addr) {
    asm volatile("ldmatrix.sync.aligned.m8n8.x4.shared.b16 {%0,%1,%2,%3}, [%4];"
        : "=r"(r[0]), "=r"(r[1]), "=r"(r[2]), "=r"(r[3]) : "r"(addr));
}
__device__ __forceinline__ void ldsm_x2(uint32_t* r, uint32_t addr) {
    asm volatile("ldmatrix.sync.aligned.m8n8.x2.shared.b16 {%0,%1}, [%2];"
        : "=r"(r[0]), "=r"(r[1]) : "r"(addr));
}
__device__ __forceinline__ void mma16816(float* d, const uint32_t* a,
                                         const uint32_t* b) {
    asm volatile("mma.sync.aligned.m16n8k16.row.col.f32.bf16.bf16.f32 "
        "{%0,%1,%2,%3}, {%4,%5,%6,%7}, {%8,%9}, {%0,%1,%2,%3};"
        : "+f"(d[0]), "+f"(d[1]), "+f"(d[2]), "+f"(d[3])
        : "r"(a[0]), "r"(a[1]), "r"(a[2]), "r"(a[3]), "r"(b[0]), "r"(b[1]));
}
__device__ __forceinline__ uint32_t pack_bf2(float a, float b) {
    __nv_bfloat162 p = __floats2bfloat162_rn(a, b);
    return *reinterpret_cast<uint32_t*>(&p);
}

// ---------------- dtype probe + edge decode (+hist fused) -------------------
__global__ void probe_kernel(const int* __restrict__ ei_w) {
    __shared__ int red[256];
    int t = threadIdx.x;
    int acc = 0;
    for (int i = t; i < 4096; i += 256) acc |= ei_w[2 * i + 1];
    red[t] = acc;
    __syncthreads();
    for (int s = 128; s > 0; s >>= 1) {
        if (t < s) red[t] |= red[t + s];
        __syncthreads();
    }
    if (t == 0) g_is64 = (red[0] == 0) ? 1 : 0;
}

__global__ void init_kernel() {
    int i = blockIdx.x * blockDim.x + threadIdx.x;
    if (i < N_NODES) { g_deg[i] = 0; g_cur[i] = 0; }
}

__global__ void convhist_kernel(const void* __restrict__ ei_raw) {
    int e = blockIdx.x * blockDim.x + threadIdx.x;
    if (e >= E_TOT) return;
    int src, dst;
    if (e < E_IN) {
        if (g_is64) {
            const long long* ei = (const long long*)ei_raw;
            src = (int)ei[e];
            dst = (int)ei[E_IN + e];
        } else {
            const int* ei = (const int*)ei_raw;
            src = ei[e];
            dst = ei[E_IN + e];
        }
    } else {
        src = dst = e - E_IN;
    }
    g_src[e] = src;
    g_dst[e] = dst;
    atomicAdd(&g_deg[dst], 1);
}

// ---------------- CSR scan + scatter ----------------------------------------
__global__ __launch_bounds__(512)
void scan1_kernel() {
    int t = threadIdx.x;
    int lane = t & 31, wid = t >> 5;
    int gid = blockIdx.x * 512 + t;
    int v = (gid < N_NODES) ? g_deg[gid] : 0;
    int x = v;
#pragma unroll
    for (int o = 1; o < 32; o <<= 1) {
        int y = __shfl_up_sync(0xFFFFFFFF, x, o);
        if (lane >= o) x += y;
    }
    __shared__ int wsum[16];
    if (lane == 31) wsum[wid] = x;
    __syncthreads();
    if (t < 16) {
        int s = wsum[t];
#pragma unroll
        for (int o = 1; o < 16; o <<= 1) {
            int y = __shfl_up_sync(0xFFFF, s, o);
            if (t >= o) s += y;
        }
        wsum[t] = s;
    }
    __syncthreads();
    int base = (wid > 0) ? wsum[wid - 1] : 0;
    if (gid < N_NODES) g_rowptr[gid] = base + x - v;
    if (t == 511) g_bsum[blockIdx.x] = base + x;
}

__global__ void scan2_kernel() {
    int t = threadIdx.x;
    int v[4]; int tot = 0;
#pragma unroll
    for (int j = 0; j < 4; j++) {
        int idx = t * 4 + j;
        v[j] = (idx < NB_TILES) ? g_bsum[idx] : 0;
        tot += v[j];
    }
    int x = tot;
#pragma unroll
    for (int o = 1; o < 32; o <<= 1) {
        int y = __shfl_up_sync(0xFFFFFFFF, x, o);
        if (t >= o) x += y;
    }
    int run = x - tot;
#pragma unroll
    for (int j = 0; j < 4; j++) {
        int idx = t * 4 + j;
        if (idx < NB_TILES) g_bscan[idx] = run;
        run += v[j];
    }
}

__global__ void scan3_kernel() {
    int i = blockIdx.x * blockDim.x + threadIdx.x;
    if (i < N_NODES) g_rowptr[i] += g_bscan[i >> 9];
    if (i == 0) g_rowptr[N_NODES] = E_TOT;
}

__global__ void scatter_kernel() {
    int e = blockIdx.x * blockDim.x + threadIdx.x;
    if (e >= E_TOT) return;
    int dst = g_dst[e];
    int pos = g_rowptr[dst] + atomicAdd(&g_cur[dst], 1);
    g_esrc[pos] = g_src[e];
}

// ---------------- W1 transpose + split --------------------------------------
__global__ void wsplit_kernel(const float* __restrict__ W1) {
    int id = blockIdx.x * blockDim.x + threadIdx.x;  // 128*512
    if (id >= F1 * F_IN) return;
    int n = id & (F1 - 1);
    int k = id >> 7;
    float v = W1[(size_t)k * F1 + n];
    __nv_bfloat16 hi = __float2bfloat16_rn(v);
    float r = v - __bfloat162float(hi);
    g_whi[n * F_IN + k] = hi;
    g_wlo[n * F_IN + k] = __float2bfloat16_rn(r);
}

// ---------------- GEMM1 via mma.sync bf16 split: h1 = X @ W1 ----------------
#define LDT 72
#define TILE_B (128 * LDT * 2)     // 18432 bytes per buffer
#define OFF_A_HI 0
#define OFF_A_LO (TILE_B)
#define OFF_B_HI (2 * TILE_B)
#define OFF_B_LO (3 * TILE_B)
#define SMEM_TOT (4 * TILE_B)

__global__ __launch_bounds__(256)
void gemm1_mma_kernel(const float* __restrict__ X) {
    extern __shared__ char smem[];
    const int t = threadIdx.x;
    const int lane = t & 31, wid = t >> 5;
    const int warp_m = wid & 3, warp_n = wid >> 2;
    const int block_row = blockIdx.x * 128;
    const uint32_t sb = smem_to_u32(smem);

    float acc[2][8][4];
#pragma unroll
    for (int i = 0; i < 2; i++)
#pragma unroll
        for (int j = 0; j < 8; j++)
#pragma unroll
            for (int q = 0; q < 4; q++) acc[i][j][q] = 0.f;

    for (int kt = 0; kt < 8; kt++) {
        const int k0g = kt * 64;
#pragma unroll
        for (int i = 0; i < 8; i++) {
            int c = i * 256 + t;
            int row = c >> 4;
            int kq = c & 15;
            int grow = block_row + row;
            float4 v = make_float4(0.f, 0.f, 0.f, 0.f);
            if (grow < N_NODES)
                v = *reinterpret_cast<const float4*>(X + (size_t)grow * F_IN + k0g + kq * 4);
            uint2 hi, lo;
            hi.x = pack_bf2(v.x, v.y);
            hi.y = pack_bf2(v.z, v.w);
            __nv_bfloat16 hx = __float2bfloat16_rn(v.x);
            __nv_bfloat16 hy = __float2bfloat16_rn(v.y);
            __nv_bfloat16 hz = __float2bfloat16_rn(v.z);
            __nv_bfloat16 hw = __float2bfloat16_rn(v.w);
            lo.x = pack_bf2(v.x - __bfloat162float(hx), v.y - __bfloat162float(hy));
            lo.y = pack_bf2(v.z - __bfloat162float(hz), v.w - __bfloat162float(hw));
            int off = row * 144 + kq * 8;
            *reinterpret_cast<uint2*>(smem + OFF_A_HI + off) = hi;
            *reinterpret_cast<uint2*>(smem + OFF_A_LO + off) = lo;
        }
#pragma unroll
        for (int i = 0; i < 4; i++) {
            int c = i * 256 + t;
            int n = c >> 3;
            int kq = c & 7;
            uint4 vh = *reinterpret_cast<const uint4*>(g_whi + (size_t)n * F_IN + k0g + kq * 8);
            uint4 vl = *reinterpret_cast<const uint4*>(g_wlo + (size_t)n * F_IN + k0g + kq * 8);
            int off = n * 144 + kq * 16;
            *reinterpret_cast<uint4*>(smem + OFF_B_HI + off) = vh;
            *reinterpret_cast<uint4*>(smem + OFF_B_LO + off) = vl;
        }
        __syncthreads();

#pragma unroll
        for (int ks = 0; ks < 4; ks++) {
            const int k0 = ks * 16;
            uint32_t ah[2][4], al[2][4], bh[8][2], bl[8][2];
#pragma unroll
            for (int mf = 0; mf < 2; mf++) {
                int m0 = warp_m * 32 + mf * 16;
                uint32_t addr = (uint32_t)((m0 + (lane & 15)) * 144 +
                                           (k0 + (lane >> 4) * 8) * 2);
                ldsm_x4(ah[mf], sb + OFF_A_HI + addr);
                ldsm_x4(al[mf], sb + OFF_A_LO + addr);
            }
#pragma unroll
            for (int nf = 0; nf < 8; nf++) {
                int n0 = warp_n * 64 + nf * 8;
                uint32_t addr = (uint32_t)((n0 + (lane & 7)) * 144 +
                                           (k0 + ((lane >> 3) & 1) * 8) * 2);
                ldsm_x2(bh[nf], sb + OFF_B_HI + addr);
                ldsm_x2(bl[nf], sb + OFF_B_LO + addr);
            }
#pragma unroll
            for (int mf = 0; mf < 2; mf++)
#pragma unroll
                for (int nf = 0; nf < 8; nf++) {
                    mma16816(acc[mf][nf], ah[mf], bh[nf]);
                    mma16816(acc[mf][nf], ah[mf], bl[nf]);
                    mma16816(acc[mf][nf], al[mf], bh[nf]);
                }
        }
        __syncthreads();
    }

#pragma unroll
    for (int mf = 0; mf < 2; mf++) {
        int r0 = block_row + warp_m * 32 + mf * 16 + (lane >> 2);
#pragma unroll
        for (int nf = 0; nf < 8; nf++) {
            int col = warp_n * 64 + nf * 8 + (lane & 3) * 2;
            if (r0 < N_NODES)
                *reinterpret_cast<float2*>(g_h1 + (size_t)r0 * F1 + col) =
                    make_float2(acc[mf][nf][0], acc[mf][nf][1]);
            if (r0 + 8 < N_NODES)
                *reinterpret_cast<float2*>(g_h1 + (size_t)(r0 + 8) * F1 + col) =
                    make_float2(acc[mf][nf][2], acc[mf][nf][3]);
        }
    }
}

// ---------------- attention dots, layer 1 -----------------------------------
__global__ void attn1_kernel(const float* __restrict__ att_src,
                             const float* __restrict__ att_dst) {
    int id = blockIdx.x * blockDim.x + threadIdx.x;   // n*8 + h
    if (id >= N_NODES * H1) return;
    int n = id >> 3, h = id & 7;
    const float* row = g_h1 + (size_t)n * F1 + h * C1;
    float s = 0.f, d = 0.f;
#pragma unroll
    for (int c = 0; c < C1; c++) {
        float v = row[c];
        s += v * att_src[h * C1 + c];
        d += v * att_dst[h * C1 + c];
    }
    g_asrc1[id] = s;
    g_adst1[id] = d;
}

// ---------------- layer-1 aggregation: warp per dst node, online softmax ----
__global__ __launch_bounds__(256)
void agg1_kernel(const float* __restrict__ b1) {
    int gid  = blockIdx.x * blockDim.x + threadIdx.x;
    int n    = gid >> 5;
    int lane = gid & 31;
    if (n >= N_NODES) return;
    int h = lane >> 2;
    float adst = g_adst1[n * H1 + h];
    int beg = g_rowptr[n], end = g_rowptr[n + 1];

    float m = -INFINITY, d = 0.f;
    float ax = 0.f, ay = 0.f, az = 0.f, aw = 0.f;
    for (int i = beg; i < end; i++) {
        int src = __ldg(&g_esrc[i]);
        float v = g_asrc1[src * H1 + h] + adst;
        v = (v > 0.f) ? v : NEG_SLOPE * v;
        float mn = fmaxf(m, v);
        float s  = __expf(m - mn);
        float w  = __expf(v - mn);
        const float4 hv = *reinterpret_cast<const float4*>(g_h1 + (size_t)src * F1 + lane * 4);
        d  = d  * s + w;
        ax = ax * s + w * hv.x;
        ay = ay * s + w * hv.y;
        az = az * s + w * hv.z;
        aw = aw * s + w * hv.w;
        m = mn;
    }
    float inv = 1.f / (d + 1e-16f);
    const float4 bv = *reinterpret_cast<const float4*>(b1 + lane * 4);
    float o0 = ax * inv + bv.x;
    float o1 = ay * inv + bv.y;
    float o2 = az * inv + bv.z;
    float o3 = aw * inv + bv.w;
    o0 = (o0 > 0.f) ? o0 : (__expf(o0) - 1.f);
    o1 = (o1 > 0.f) ? o1 : (__expf(o1) - 1.f);
    o2 = (o2 > 0.f) ? o2 : (__expf(o2) - 1.f);
    o3 = (o3 > 0.f) ? o3 : (__expf(o3) - 1.f);
    *reinterpret_cast<float4*>(g_out1 + (size_t)n * F1 + lane * 4) =
        make_float4(o0, o1, o2, o3);
}

// ------- GEMM2 (+ fused attn2 dots): h2 = out1 @ W2, asrc2/adst2 -----------
__global__ __launch_bounds__(256)
void gemm2_kernel(const float* __restrict__ W2,
                  const float* __restrict__ att_src,
                  const float* __restrict__ att_dst) {
    __shared__ float Ws[F1 * C2];
    __shared__ float Hs[32][F1];
    const int t  = threadIdx.x;
    const int nb = blockIdx.x * 32;
    for (int i = t; i < F1 * C2; i += 256) Ws[i] = W2[i];
    for (int i = t; i < 32 * F1; i += 256) {
        int r = i >> 7, c = i & 127;
        int n = nb + r;
        Hs[r][c] = (n < N_NODES) ? g_out1[(size_t)n * F1 + c] : 0.f;
    }
    __syncthreads();
    const int ln = t >> 3;
    const int c0 = (t & 7) * 5;
    float acc[5] = {0.f, 0.f, 0.f, 0.f, 0.f};
    for (int k = 0; k < F1; k++) {
        float hv = Hs[ln][k];
#pragma unroll
        for (int j = 0; j < 5; j++) acc[j] += hv * Ws[k * C2 + c0 + j];
    }
    int n = nb + ln;
    if (n < N_NODES) {
#pragma unroll
        for (int j = 0; j < 5; j++) g_h2[(size_t)n * C2 + c0 + j] = acc[j];
    }
    // fused attn2 dot-products (reduce across the 8 lanes owning this node)
    float s = 0.f, d = 0.f;
#pragma unroll
    for (int j = 0; j < 5; j++) {
        s += acc[j] * att_src[c0 + j];
        d += acc[j] * att_dst[c0 + j];
    }
#pragma unroll
    for (int o = 4; o > 0; o >>= 1) {
        s += __shfl_xor_sync(0xFFFFFFFF, s, o);
        d += __shfl_xor_sync(0xFFFFFFFF, d, o);
    }
    if ((t & 7) == 0 && n < N_NODES) {
        g_asrc2[n] = s;
        g_adst2[n] = d;
    }
}

// -------- layer-2 aggregation + bias + log_softmax (warp per dst node) ------
__global__ __launch_bounds__(256)
void agg2_kernel(const float* __restrict__ b2, float* __restrict__ out) {
    int gid  = blockIdx.x * blockDim.x + threadIdx.x;
    int n    = gid >> 5;
    int lane = gid & 31;
    if (n >= N_NODES) return;
    float adst = g_adst2[n];
    int beg = g_rowptr[n], end = g_rowptr[n + 1];

    float m = -INFINITY, d = 0.f;
    float a1 = 0.f, a2 = 0.f;
    for (int i = beg; i < end; i++) {
        int src = __ldg(&g_esrc[i]);
        float v = g_asrc2[src] + adst;
        v = (v > 0.f) ? v : NEG_SLOPE * v;
        float mn = fmaxf(m, v);
        float s  = __expf(m - mn);
        float w  = __expf(v - mn);
        const float* hrow = g_h2 + (size_t)src * C2;
        float h1v = hrow[lane];
        float h2v = (lane < C2 - 32) ? hrow[lane + 32] : 0.f;
        d  = d  * s + w;
        a1 = a1 * s + w * h1v;
        a2 = a2 * s + w * h2v;
        m = mn;
    }
    float inv = 1.f / (d + 1e-16f);
    float v1 = a1 * inv + b2[lane];
    float v2 = (lane < C2 - 32) ? (a2 * inv + b2[lane + 32]) : -INFINITY;

    float mm = fmaxf(v1, v2);
#pragma unroll
    for (int o = 16; o > 0; o >>= 1) mm = fmaxf(mm, __shfl_xor_sync(0xFFFFFFFF, mm, o));
    float ss = __expf(v1 - mm) + ((lane < C2 - 32) ? __expf(v2 - mm) : 0.f);
#pragma unroll
    for (int o = 16; o > 0; o >>= 1) ss += __shfl_xor_sync(0xFFFFFFFF, ss, o);
    float lse = mm + logf(ss);
    out[(size_t)n * C2 + lane] = v1 - lse;
    if (lane < C2 - 32) out[(size_t)n * C2 + lane + 32] = v2 - lse;
}

// ---------------- launcher ---------------------------------------------------
extern "C" void kernel_launch(void* const* d_in, const int* in_sizes, int n_in,
                              void* d_out, int out_size) {
    const float* x        = (const float*)d_in[0];
    const void*  ei       = d_in[1];
    const float* W1       = (const float*)d_in[2];
    const float* att_src1 = (const float*)d_in[3];
    const float* att_dst1 = (const float*)d_in[4];
    const float* b1       = (const float*)d_in[5];
    const float* W2       = (const float*)d_in[6];
    const float* att_src2 = (const float*)d_in[7];
    const float* att_dst2 = (const float*)d_in[8];
    const float* b2       = (const float*)d_in[9];
    float*       out      = (float*)d_out;

    const int T = 256;

    static cudaStream_t s1 = 0;
    static cudaEvent_t ev_fork = 0, ev_join = 0;
    static int inited = 0;
    if (!inited) {
        cudaFuncSetAttribute(gemm1_mma_kernel,
                             cudaFuncAttributeMaxDynamicSharedMemorySize, SMEM_TOT);
        cudaStreamCreateWithFlags(&s1, cudaStreamNonBlocking);
        cudaEventCreateWithFlags(&ev_fork, cudaEventDisableTiming);
        cudaEventCreateWithFlags(&ev_join, cudaEventDisableTiming);
        inited = 1;
    }

    // main stream: dtype probe, then fork CSR build to side stream
    probe_kernel<<<1, 256>>>((const int*)ei);
    cudaEventRecord(ev_fork, 0);
    cudaStreamWaitEvent(s1, ev_fork, 0);

    // side stream: CSR-by-dst build (hidden under gemm1)
    init_kernel<<<(N_NODES + T - 1) / T, T, 0, s1>>>();
    convhist_kernel<<<(E_TOT + T - 1) / T, T, 0, s1>>>(ei);
    scan1_kernel<<<NB_TILES, 512, 0, s1>>>();
    scan2_kernel<<<1, 32, 0, s1>>>();
    scan3_kernel<<<(N_NODES + T - 1) / T, T, 0, s1>>>();
    scatter_kernel<<<(E_TOT + T - 1) / T, T, 0, s1>>>();
    cudaEventRecord(ev_join, s1);

    // main stream: dense path
    wsplit_kernel<<<(F1 * F_IN + T - 1) / T, T>>>(W1);
    gemm1_mma_kernel<<<(N_NODES + 127) / 128, 256, SMEM_TOT>>>(x);
    attn1_kernel<<<(N_NODES * H1 + T - 1) / T, T>>>(att_src1, att_dst1);

    // join: aggregation needs the CSR
    cudaStreamWaitEvent(0, ev_join, 0);
    agg1_kernel<<<((size_t)N_NODES * 32 + T - 1) / T, T>>>(b1);

    gemm2_kernel<<<(N_NODES + 31) / 32, 256>>>(W2, att_src2, att_dst2);
    agg2_kernel<<<((size_t)N_NODES * 32 + T - 1) / T, T>>>(b2, out);
}